// round 1
// baseline (speedup 1.0000x reference)
#include <cuda_runtime.h>
#include <cstdint>

#define BB 4
#define TT 2048
#define CC 1024
#define HH 16
#define DD 64
#define BT_ (BB*TT)      // 8192
#define N3C (3*CC)       // 3072

// Scratch (allocation-free rule: __device__ globals)
__device__ float g_q[BB*HH*TT*DD];     // [B,H,T,D]
__device__ float g_k[BB*HH*TT*DD];
__device__ float g_v[BB*HH*TT*DD];
__device__ float g_att[BT_*CC];        // [B*T, C] attention output

// ---------------------------------------------------------------------------
// GEMM1: qkv = X[8192,1024] @ W[1024,3072] + b, scattered into q/k/v [B,H,T,D]
// 128x128x8 tile, 256 threads, 8x8 micro-tile (2x2 groups of 4x4, stride 64).
// ---------------------------------------------------------------------------
__global__ __launch_bounds__(256, 2)
void qkv_gemm_kernel(const float* __restrict__ X,
                     const float* __restrict__ W,
                     const float* __restrict__ bias)
{
    __shared__ float As[8][132];   // [k][m], padded
    __shared__ float Bs[8][128];   // [k][n]

    const int tid = threadIdx.x;
    const int tx = tid & 15, ty = tid >> 4;
    const int bM = blockIdx.y * 128;
    const int bN = blockIdx.x * 128;

    const int aRow = tid >> 1;
    const int aCol = (tid & 1) * 4;
    const int bRow = tid >> 5;
    const int bCol = (tid & 31) * 4;

    const float* Ap = X + (size_t)(bM + aRow) * CC + aCol;
    const float* Bp = W + (size_t)bRow * N3C + bN + bCol;

    float acc[2][2][4][4];
    #pragma unroll
    for (int a = 0; a < 2; a++)
        #pragma unroll
        for (int b = 0; b < 2; b++)
            #pragma unroll
            for (int i = 0; i < 4; i++)
                #pragma unroll
                for (int j = 0; j < 4; j++) acc[a][b][i][j] = 0.f;

    for (int k0 = 0; k0 < CC; k0 += 8) {
        float4 av = *(const float4*)(Ap + k0);
        As[aCol+0][aRow] = av.x;
        As[aCol+1][aRow] = av.y;
        As[aCol+2][aRow] = av.z;
        As[aCol+3][aRow] = av.w;
        float4 bv = *(const float4*)(Bp + (size_t)k0 * N3C);
        *(float4*)&Bs[bRow][bCol] = bv;
        __syncthreads();
        #pragma unroll
        for (int k = 0; k < 8; k++) {
            float4 a0 = *(const float4*)&As[k][ty*4];
            float4 a1 = *(const float4*)&As[k][ty*4 + 64];
            float4 b0 = *(const float4*)&Bs[k][tx*4];
            float4 b1 = *(const float4*)&Bs[k][tx*4 + 64];
            float ar[2][4] = {{a0.x,a0.y,a0.z,a0.w},{a1.x,a1.y,a1.z,a1.w}};
            float br[2][4] = {{b0.x,b0.y,b0.z,b0.w},{b1.x,b1.y,b1.z,b1.w}};
            #pragma unroll
            for (int ri = 0; ri < 2; ri++)
                #pragma unroll
                for (int ci = 0; ci < 2; ci++)
                    #pragma unroll
                    for (int i = 0; i < 4; i++)
                        #pragma unroll
                        for (int j = 0; j < 4; j++)
                            acc[ri][ci][i][j] += ar[ri][i] * br[ci][j];
        }
        __syncthreads();
    }

    // Epilogue: bias + scatter into q/k/v [B,H,T,D]
    #pragma unroll
    for (int ci = 0; ci < 2; ci++) {
        int gcol  = bN + ci*64 + tx*4;
        int which = gcol >> 10;          // 0=q, 1=k, 2=v
        int rem   = gcol & 1023;
        int h     = rem >> 6;
        int dbase = rem & 63;
        float* dst = (which == 0) ? g_q : (which == 1 ? g_k : g_v);
        float4 bz = *(const float4*)(bias + gcol);
        #pragma unroll
        for (int ri = 0; ri < 2; ri++) {
            #pragma unroll
            for (int i = 0; i < 4; i++) {
                int row = bM + ri*64 + ty*4 + i;
                int b_  = row >> 11;             // / TT
                int t_  = row & (TT - 1);
                float4 o;
                o.x = acc[ri][ci][i][0] + bz.x;
                o.y = acc[ri][ci][i][1] + bz.y;
                o.z = acc[ri][ci][i][2] + bz.z;
                o.w = acc[ri][ci][i][3] + bz.w;
                *(float4*)(dst + ((size_t)(b_*HH + h)*TT + t_)*DD + dbase) = o;
            }
        }
    }
}

// ---------------------------------------------------------------------------
// Flash attention: per (b,h, 64-row q-block). BM=64, BN=64, D=64. 128 threads.
// Thread (ty 0..7, tx 0..15): S rows ty*8+i (i<8), cols tx+16j (j<4).
// Online softmax fully in registers via 16-lane shfl reductions.
// ---------------------------------------------------------------------------
#define ATT_SMEM ((64*64 + 64*65 + 64*64) * 4)   // Qs + KVs(pitch65) + Ps

__global__ __launch_bounds__(128, 4)
void attn_kernel()
{
    extern __shared__ float sm[];
    float* Qs  = sm;                   // [64][64]
    float* KVs = sm + 64*64;           // [64][65] (K, then reused for V)
    float* Ps  = sm + 64*64 + 64*65;   // [64][64]

    const int tid = threadIdx.x;
    const int tx = tid & 15, ty = tid >> 4;
    const int qb = blockIdx.x;         // 0..31
    const int bh = blockIdx.y;         // 0..63  (= b*H + h)
    const int b_ = bh >> 4, h = bh & 15;

    const float* Qg = g_q + ((size_t)bh * TT + qb*64) * DD;
    const float* Kg = g_k + (size_t)bh * TT * DD;
    const float* Vg = g_v + (size_t)bh * TT * DD;

    // Load Q tile (contiguous 4096 floats)
    #pragma unroll
    for (int p = 0; p < 8; p++) {
        int idx = (p*128 + tid) * 4;
        *(float4*)(Qs + idx) = *(const float4*)(Qg + idx);
    }

    float m_i[8], l_i[8], o[8][4];
    #pragma unroll
    for (int i = 0; i < 8; i++) {
        m_i[i] = __int_as_float(0xff800000);  // -inf
        l_i[i] = 0.f;
        #pragma unroll
        for (int j = 0; j < 4; j++) o[i][j] = 0.f;
    }

    const float scale = 0.125f;   // 1/sqrt(64)

    for (int kt = 0; kt < TT/64; kt++) {
        __syncthreads();                          // prev PV done; Qs visible (1st iter)
        // Load K tile into KVs (pitch 65, scalar stores)
        {
            const float* src = Kg + (size_t)kt * 64 * DD;
            #pragma unroll
            for (int p = 0; p < 8; p++) {
                int idx = (p*128 + tid) * 4;
                int c = idx >> 6, k0 = idx & 63;
                float4 v4 = *(const float4*)(src + idx);
                float* d = KVs + c*65 + k0;
                d[0] = v4.x; d[1] = v4.y; d[2] = v4.z; d[3] = v4.w;
            }
        }
        __syncthreads();                          // K visible

        // S = Q K^T (scaled)
        float s[8][4];
        #pragma unroll
        for (int i = 0; i < 8; i++)
            #pragma unroll
            for (int j = 0; j < 4; j++) s[i][j] = 0.f;

        #pragma unroll 4
        for (int k = 0; k < 64; k++) {
            float q[8], kk[4];
            #pragma unroll
            for (int i = 0; i < 8; i++) q[i] = Qs[(ty*8 + i)*64 + k];
            #pragma unroll
            for (int j = 0; j < 4; j++) kk[j] = KVs[(tx + 16*j)*65 + k];
            #pragma unroll
            for (int i = 0; i < 8; i++)
                #pragma unroll
                for (int j = 0; j < 4; j++)
                    s[i][j] += q[i] * kk[j];
        }

        // Online softmax, per row in registers (16-lane reductions)
        #pragma unroll
        for (int i = 0; i < 8; i++) {
            #pragma unroll
            for (int j = 0; j < 4; j++) s[i][j] *= scale;
            float mx = fmaxf(fmaxf(s[i][0], s[i][1]), fmaxf(s[i][2], s[i][3]));
            mx = fmaxf(mx, __shfl_xor_sync(0xffffffffu, mx, 8));
            mx = fmaxf(mx, __shfl_xor_sync(0xffffffffu, mx, 4));
            mx = fmaxf(mx, __shfl_xor_sync(0xffffffffu, mx, 2));
            mx = fmaxf(mx, __shfl_xor_sync(0xffffffffu, mx, 1));
            float mnew  = fmaxf(m_i[i], mx);
            float alpha = __expf(m_i[i] - mnew);
            m_i[i] = mnew;
            float lsum = 0.f;
            #pragma unroll
            for (int j = 0; j < 4; j++) {
                float p = __expf(s[i][j] - mnew);
                Ps[(ty*8 + i)*64 + tx + 16*j] = p;
                lsum += p;
            }
            lsum += __shfl_xor_sync(0xffffffffu, lsum, 8);
            lsum += __shfl_xor_sync(0xffffffffu, lsum, 4);
            lsum += __shfl_xor_sync(0xffffffffu, lsum, 2);
            lsum += __shfl_xor_sync(0xffffffffu, lsum, 1);
            l_i[i] = l_i[i] * alpha + lsum;
            #pragma unroll
            for (int j = 0; j < 4; j++) o[i][j] *= alpha;
        }
        __syncthreads();                          // Ps written, K reads done

        // Load V tile into KVs
        {
            const float* src = Vg + (size_t)kt * 64 * DD;
            #pragma unroll
            for (int p = 0; p < 8; p++) {
                int idx = (p*128 + tid) * 4;
                int c = idx >> 6, k0 = idx & 63;
                float4 v4 = *(const float4*)(src + idx);
                float* d = KVs + c*65 + k0;
                d[0] = v4.x; d[1] = v4.y; d[2] = v4.z; d[3] = v4.w;
            }
        }
        __syncthreads();                          // V visible

        // O += P @ V   (O cols d = tx + 16j)
        #pragma unroll 4
        for (int c = 0; c < 64; c++) {
            float pr[8], vv[4];
            #pragma unroll
            for (int j = 0; j < 4; j++) vv[j] = KVs[c*65 + tx + 16*j];
            #pragma unroll
            for (int i = 0; i < 8; i++) pr[i] = Ps[(ty*8 + i)*64 + c];
            #pragma unroll
            for (int i = 0; i < 8; i++)
                #pragma unroll
                for (int j = 0; j < 4; j++)
                    o[i][j] += pr[i] * vv[j];
        }
    }

    // Epilogue: normalize and write [B*T, C] with col = h*64 + d
    #pragma unroll
    for (int i = 0; i < 8; i++) {
        float inv = 1.f / l_i[i];
        int t_ = qb*64 + ty*8 + i;
        size_t base = ((size_t)b_ * TT + t_) * CC + h*64;
        #pragma unroll
        for (int j = 0; j < 4; j++)
            g_att[base + tx + 16*j] = o[i][j] * inv;
    }
}

// ---------------------------------------------------------------------------
// GEMM2: out = g_att[8192,1024] @ proj_w[1024,1024] + proj_b
// ---------------------------------------------------------------------------
__global__ __launch_bounds__(256, 2)
void proj_gemm_kernel(const float* __restrict__ W,
                      const float* __restrict__ bias,
                      float* __restrict__ out)
{
    __shared__ float As[8][132];
    __shared__ float Bs[8][128];

    const int tid = threadIdx.x;
    const int tx = tid & 15, ty = tid >> 4;
    const int bM = blockIdx.y * 128;
    const int bN = blockIdx.x * 128;

    const int aRow = tid >> 1;
    const int aCol = (tid & 1) * 4;
    const int bRow = tid >> 5;
    const int bCol = (tid & 31) * 4;

    const float* Ap = g_att + (size_t)(bM + aRow) * CC + aCol;
    const float* Bp = W + (size_t)bRow * CC + bN + bCol;

    float acc[2][2][4][4];
    #pragma unroll
    for (int a = 0; a < 2; a++)
        #pragma unroll
        for (int b = 0; b < 2; b++)
            #pragma unroll
            for (int i = 0; i < 4; i++)
                #pragma unroll
                for (int j = 0; j < 4; j++) acc[a][b][i][j] = 0.f;

    for (int k0 = 0; k0 < CC; k0 += 8) {
        float4 av = *(const float4*)(Ap + k0);
        As[aCol+0][aRow] = av.x;
        As[aCol+1][aRow] = av.y;
        As[aCol+2][aRow] = av.z;
        As[aCol+3][aRow] = av.w;
        float4 bv = *(const float4*)(Bp + (size_t)k0 * CC);
        *(float4*)&Bs[bRow][bCol] = bv;
        __syncthreads();
        #pragma unroll
        for (int k = 0; k < 8; k++) {
            float4 a0 = *(const float4*)&As[k][ty*4];
            float4 a1 = *(const float4*)&As[k][ty*4 + 64];
            float4 b0 = *(const float4*)&Bs[k][tx*4];
            float4 b1 = *(const float4*)&Bs[k][tx*4 + 64];
            float ar[2][4] = {{a0.x,a0.y,a0.z,a0.w},{a1.x,a1.y,a1.z,a1.w}};
            float br[2][4] = {{b0.x,b0.y,b0.z,b0.w},{b1.x,b1.y,b1.z,b1.w}};
            #pragma unroll
            for (int ri = 0; ri < 2; ri++)
                #pragma unroll
                for (int ci = 0; ci < 2; ci++)
                    #pragma unroll
                    for (int i = 0; i < 4; i++)
                        #pragma unroll
                        for (int j = 0; j < 4; j++)
                            acc[ri][ci][i][j] += ar[ri][i] * br[ci][j];
        }
        __syncthreads();
    }

    #pragma unroll
    for (int ci = 0; ci < 2; ci++) {
        int gcol = bN + ci*64 + tx*4;
        float4 bz = *(const float4*)(bias + gcol);
        #pragma unroll
        for (int ri = 0; ri < 2; ri++) {
            #pragma unroll
            for (int i = 0; i < 4; i++) {
                int row = bM + ri*64 + ty*4 + i;
                float4 ov;
                ov.x = acc[ri][ci][i][0] + bz.x;
                ov.y = acc[ri][ci][i][1] + bz.y;
                ov.z = acc[ri][ci][i][2] + bz.z;
                ov.w = acc[ri][ci][i][3] + bz.w;
                *(float4*)(out + (size_t)row * CC + gcol) = ov;
            }
        }
    }
}

// ---------------------------------------------------------------------------
extern "C" void kernel_launch(void* const* d_in, const int* in_sizes, int n_in,
                              void* d_out, int out_size)
{
    const float* x      = (const float*)d_in[0];
    const float* qkv_w  = (const float*)d_in[1];
    const float* qkv_b  = (const float*)d_in[2];
    const float* proj_w = (const float*)d_in[3];
    const float* proj_b = (const float*)d_in[4];
    float* out = (float*)d_out;
    (void)in_sizes; (void)n_in; (void)out_size;

    cudaFuncSetAttribute(attn_kernel,
                         cudaFuncAttributeMaxDynamicSharedMemorySize, ATT_SMEM);

    qkv_gemm_kernel<<<dim3(N3C/128, BT_/128), 256>>>(x, qkv_w, qkv_b);
    attn_kernel<<<dim3(TT/64, BB*HH), 128, ATT_SMEM>>>();
    proj_gemm_kernel<<<dim3(CC/128, BT_/128), 256>>>(proj_w, proj_b, out);
}